// round 4
// baseline (speedup 1.0000x reference)
#include <cuda_runtime.h>
#include <cstdint>

// ---------------- problem constants ----------------
#define NF_DIM 8192
#define NX_DIM 2048
#define M_DIM  8192
#define BKB    128                // K elements (bytes) per mainloop iter
#define NITER  (NX_DIM / BKB)     // 16
#define NSTAGE 3
#define STAGE_BYTES 49152         // X1 16K | X2 16K | D 16K
#define SCALE_BYTES 16384         // [32 groups][128 n] fp32
#define SMEM_BYTES (NSTAGE * STAGE_BYTES + SCALE_BYTES + 1024)

// ---------------- scratch (device globals; no cudaMalloc allowed) ----------------
static __device__ __align__(256) int8_t g_X1[(size_t)M_DIM * NX_DIM];  // digit 1 of x
static __device__ __align__(256) int8_t g_X2[(size_t)M_DIM * NX_DIM];  // digit 2 of x
static __device__ __align__(256) int8_t g_D [(size_t)NF_DIM * NX_DIM]; // q - z (exact)
static __device__ float g_SX[M_DIM];                                   // sx/128 per row

// ---------------- helpers ----------------
static __device__ __forceinline__ uint32_t smem_u32(const void* p) {
    uint32_t a;
    asm("{ .reg .u64 t; cvta.to.shared.u64 t, %1; cvt.u32.u64 %0, t; }" : "=r"(a) : "l"(p));
    return a;
}
#define SWZ(o) ((o) ^ ((((uint32_t)(o)) >> 3) & 0x70u))

static __device__ __forceinline__ void cpasync16(uint32_t s, const void* g) {
    asm volatile("cp.async.cg.shared.global [%0], [%1], 16;" :: "r"(s), "l"(g));
}
static __device__ __forceinline__ void cp_commit() {
    asm volatile("cp.async.commit_group;" ::: "memory");
}
static __device__ __forceinline__ void cp_wait1() {
    asm volatile("cp.async.wait_group 1;" ::: "memory");
}
static __device__ __forceinline__ void ldm4(uint32_t* r, uint32_t addr) {
    asm volatile("ldmatrix.sync.aligned.m8n8.x4.shared.b16 {%0,%1,%2,%3}, [%4];"
                 : "=r"(r[0]), "=r"(r[1]), "=r"(r[2]), "=r"(r[3]) : "r"(addr));
}
// p = A*B (+0)
static __device__ __forceinline__ void imma0(int* d, const uint32_t* a, uint32_t b0, uint32_t b1) {
    asm volatile(
        "mma.sync.aligned.m16n8k32.row.col.s32.s8.s8.s32 "
        "{%0,%1,%2,%3}, {%4,%5,%6,%7}, {%8,%9}, {%10,%11,%12,%13};"
        : "=r"(d[0]), "=r"(d[1]), "=r"(d[2]), "=r"(d[3])
        : "r"(a[0]), "r"(a[1]), "r"(a[2]), "r"(a[3]), "r"(b0), "r"(b1),
          "r"(0), "r"(0), "r"(0), "r"(0));
}
// p += A*B
static __device__ __forceinline__ void imma(int* d, const uint32_t* a, uint32_t b0, uint32_t b1) {
    asm volatile(
        "mma.sync.aligned.m16n8k32.row.col.s32.s8.s8.s32 "
        "{%0,%1,%2,%3}, {%4,%5,%6,%7}, {%8,%9}, {%0,%1,%2,%3};"
        : "+r"(d[0]), "+r"(d[1]), "+r"(d[2]), "+r"(d[3])
        : "r"(a[0]), "r"(a[1]), "r"(a[2]), "r"(a[3]), "r"(b0), "r"(b1));
}

// ---------------- prep 1: row-scaled 2-digit s8 quantization of x ----------------
// One block per row (256 thr x 8 elems).
__global__ __launch_bounds__(256) void prep_x_kernel(const float* __restrict__ x) {
    const int m = blockIdx.x, tid = threadIdx.x;
    const float* rp = x + (size_t)m * NX_DIM + tid * 8;
    float4 u0 = *(const float4*)rp;
    float4 u1 = *(const float4*)(rp + 4);
    float v[8] = {u0.x, u0.y, u0.z, u0.w, u1.x, u1.y, u1.z, u1.w};

    float mx = 0.f;
    #pragma unroll
    for (int i = 0; i < 8; i++) mx = fmaxf(mx, fabsf(v[i]));
    #pragma unroll
    for (int o = 16; o; o >>= 1) mx = fmaxf(mx, __shfl_xor_sync(~0u, mx, o));
    __shared__ float wm[8];
    if ((tid & 31) == 0) wm[tid >> 5] = mx;
    __syncthreads();
    float gmx = wm[0];
    #pragma unroll
    for (int i = 1; i < 8; i++) gmx = fmaxf(gmx, wm[i]);
    gmx = fmaxf(gmx, 1e-20f);
    const float inv = 127.0f / gmx;

    uint32_t w1a = 0, w1b = 0, w2a = 0, w2b = 0;
    #pragma unroll
    for (int i = 0; i < 8; i++) {
        float f = v[i] * inv;
        int q1 = __float2int_rn(f);
        int q2 = __float2int_rn((f - (float)q1) * 128.0f);
        uint32_t b1 = (uint32_t)(q1 & 255), b2 = (uint32_t)(q2 & 255);
        if (i < 4) { w1a |= b1 << (8 * i);       w2a |= b2 << (8 * i); }
        else       { w1b |= b1 << (8 * (i - 4)); w2b |= b2 << (8 * (i - 4)); }
    }
    uint2 o1; o1.x = w1a; o1.y = w1b;
    uint2 o2; o2.x = w2a; o2.y = w2b;
    *(uint2*)(g_X1 + (size_t)m * NX_DIM + tid * 8) = o1;
    *(uint2*)(g_X2 + (size_t)m * NX_DIM + tid * 8) = o2;
    if (tid == 0) g_SX[m] = gmx * (1.0f / (127.0f * 128.0f));
}

// ---------------- prep 2: exact int4 -> s8 (q - z) ----------------
__global__ __launch_bounds__(256) void prep_w_kernel(const int* __restrict__ packed,
                                                     const int* __restrict__ zeros) {
    size_t i = (size_t)blockIdx.x * blockDim.x + threadIdx.x;  // over 8192*1024/4
    int4 p = ((const int4*)packed)[i];
    int n  = (int)((i * 4) >> 10);
    int j0 = (int)((i * 4) & 1023);
    int z  = zeros[n * 32 + (j0 >> 5)];

    int pp[4] = {p.x, p.y, p.z, p.w};
    uint32_t wa = 0, wb = 0;
    #pragma unroll
    for (int q = 0; q < 4; q++) {
        int b0 = (pp[q] & 15) - z;
        int b1 = ((pp[q] >> 4) & 15) - z;
        uint32_t pack = (uint32_t)(b0 & 255) | ((uint32_t)(b1 & 255) << 8);
        if (q < 2) wa |= pack << (16 * q);
        else       wb |= pack << (16 * (q - 2));
    }
    uint2 o; o.x = wa; o.y = wb;
    *(uint2*)(g_D + (size_t)n * NX_DIM + j0 * 2) = o;
}

// ---------------- GEMM: group-scaled 2-digit s8 IMMA ----------------
// 256 threads = 8 warps, warp grid 2(M) x 4(N), warp tile 64x32.
__global__ __launch_bounds__(256, 1)
void gemm_kernel(float* __restrict__ out, const float* __restrict__ scales,
                 const float* __restrict__ bias) {
    extern __shared__ char smem[];
    const uint32_t sb = smem_u32(smem);
    const uint32_t TILE0 = (sb + 1023) & ~1023u;
    float* sscale = (float*)(smem + (TILE0 - sb) + NSTAGE * STAGE_BYTES);  // [32][128]

    const int tid = threadIdx.x;
    const int wid = tid >> 5, lid = tid & 31;
    const int warp_m = wid & 1;
    const int warp_n = wid >> 1;

    const int t  = blockIdx.x;
    const int bm = ((t >> 9) << 3) | (t & 7);   // 8-wide M supertiles: B panel L2-resident
    const int bn = (t >> 3) & 63;

    const char* gX1 = (const char*)(g_X1 + (size_t)bm * 128 * NX_DIM);
    const char* gX2 = (const char*)(g_X2 + (size_t)bm * 128 * NX_DIM);
    const char* gD  = (const char*)(g_D  + (size_t)bn * 128 * NX_DIM);

    // scales tile -> smem transposed: sscale[g][n_local]
    if (tid < 128) {
        const float4* src = (const float4*)(scales + (size_t)(bn * 128 + tid) * 32);
        #pragma unroll
        for (int i = 0; i < 8; i++) {
            float4 s4 = src[i];
            sscale[(i * 4 + 0) * 128 + tid] = s4.x;
            sscale[(i * 4 + 1) * 128 + tid] = s4.y;
            sscale[(i * 4 + 2) * 128 + tid] = s4.z;
            sscale[(i * 4 + 3) * 128 + tid] = s4.w;
        }
    }

    const int lrow = tid >> 3;   // 0..31
    const int lseg = tid & 7;    // 16B segment within 128B row

    auto load_stage = [&](int j, int slot) {
        const uint32_t s0 = TILE0 + slot * STAGE_BYTES;
        #pragma unroll
        for (int i = 0; i < 4; i++) {
            const int row = lrow + i * 32;
            const uint32_t so = SWZ((uint32_t)(row * 128 + lseg * 16));
            const size_t go = (size_t)row * NX_DIM + j * BKB + lseg * 16;
            cpasync16(s0 +         so, gX1 + go);
            cpasync16(s0 + 16384 + so, gX2 + go);
            cpasync16(s0 + 32768 + so, gD  + go);
        }
        cp_commit();
    };

    float acc[4][4][4];
    #pragma unroll
    for (int a = 0; a < 4; a++)
        #pragma unroll
        for (int b = 0; b < 4; b++)
            #pragma unroll
            for (int c = 0; c < 4; c++) acc[a][b][c] = 0.f;

    // ldmatrix lane addressing (byte offsets)
    const int laneA_row = (lid & 7) + ((lid >> 3) & 1) * 8;
    const int laneA_k   = ((lid >> 4) & 1) * 16;
    const int laneB_row = (lid & 7) + ((lid >> 4) & 1) * 8;
    const int laneB_k   = ((lid >> 3) & 1) * 16;

    load_stage(0, 0);
    load_stage(1, 1);
    __syncthreads();  // also covers sscale writes

    #pragma unroll 1
    for (int j = 0; j < NITER; j++) {
        cp_wait1();
        __syncthreads();
        if (j + 2 < NITER) load_stage(j + 2, (j + 2) % NSTAGE);
        else cp_commit();   // keep wait_group accounting valid

        const uint32_t s0 = TILE0 + (j % NSTAGE) * STAGE_BYTES;
        const uint32_t X1b = s0, X2b = s0 + 16384, Db = s0 + 32768;

        #pragma unroll
        for (int g2 = 0; g2 < 2; g2++) {
            const int kb0 = g2 * 64;
            const int g   = j * 2 + g2;

            // B fragments: bfr[ks][half]: r0,r1 = (b0,b1) of n-tile half*2; r2,r3 half*2+1
            uint32_t bfr[2][2][4];
            #pragma unroll
            for (int ks = 0; ks < 2; ks++)
                #pragma unroll
                for (int h = 0; h < 2; h++) {
                    const uint32_t off = SWZ((uint32_t)((warp_n * 32 + h * 16 + laneB_row) * 128
                                                        + kb0 + ks * 32 + laneB_k));
                    ldm4(bfr[ks][h], Db + off);
                }

            // group scales: float2 per nt
            float2 sc[4];
            #pragma unroll
            for (int nt = 0; nt < 4; nt++)
                sc[nt] = *(float2*)(sscale + g * 128 + warp_n * 32 + nt * 8 + (lid & 3) * 2);

            #pragma unroll
            for (int mt = 0; mt < 4; mt++) {
                uint32_t a1[2][4], a2[2][4];
                #pragma unroll
                for (int ks = 0; ks < 2; ks++) {
                    const uint32_t off = SWZ((uint32_t)((warp_m * 64 + mt * 16 + laneA_row) * 128
                                                        + kb0 + ks * 32 + laneA_k));
                    ldm4(a1[ks], X1b + off);
                    ldm4(a2[ks], X2b + off);
                }
                #pragma unroll
                for (int nt = 0; nt < 4; nt++) {
                    const uint32_t b00 = bfr[0][nt >> 1][(nt & 1) * 2];
                    const uint32_t b01 = bfr[0][nt >> 1][(nt & 1) * 2 + 1];
                    const uint32_t b10 = bfr[1][nt >> 1][(nt & 1) * 2];
                    const uint32_t b11 = bfr[1][nt >> 1][(nt & 1) * 2 + 1];
                    int p1[4], p2[4];
                    imma0(p1, a1[0], b00, b01);
                    imma (p1, a1[1], b10, b11);
                    imma0(p2, a2[0], b00, b01);
                    imma (p2, a2[1], b10, b11);
                    #pragma unroll
                    for (int r = 0; r < 4; r++) {
                        const float pf = (float)(p1[r] * 128 + p2[r]);  // exact, |p| < 2^24
                        const float s  = (r & 1) ? sc[nt].y : sc[nt].x;
                        acc[mt][nt][r] = fmaf(pf, s, acc[mt][nt][r]);
                    }
                }
            }
        }
    }

    // ---- epilogue: out = (sx/128) * acc + bias ----
    const int gm0 = bm * 128 + warp_m * 64 + (lid >> 2);
    const int gn0 = bn * 128 + warp_n * 32 + (lid & 3) * 2;
    #pragma unroll
    for (int mt = 0; mt < 4; mt++) {
        const int gm = gm0 + mt * 16;
        const float sx0 = g_SX[gm];
        const float sx1 = g_SX[gm + 8];
        #pragma unroll
        for (int nt = 0; nt < 4; nt++) {
            const int gn = gn0 + nt * 8;
            const float2 bv = *(const float2*)(bias + gn);
            float2 v0, v1;
            v0.x = fmaf(acc[mt][nt][0], sx0, bv.x);
            v0.y = fmaf(acc[mt][nt][1], sx0, bv.y);
            v1.x = fmaf(acc[mt][nt][2], sx1, bv.x);
            v1.y = fmaf(acc[mt][nt][3], sx1, bv.y);
            *(float2*)(out + (size_t)gm * NF_DIM + gn)       = v0;
            *(float2*)(out + (size_t)(gm + 8) * NF_DIM + gn) = v1;
        }
    }
}

// ---------------- launch ----------------
extern "C" void kernel_launch(void* const* d_in, const int* in_sizes, int n_in,
                              void* d_out, int out_size) {
    const float* x      = (const float*)d_in[0];
    const int*   packed = (const int*)d_in[1];
    const float* scales = (const float*)d_in[2];
    const int*   zeros  = (const int*)d_in[3];
    const float* bias   = (const float*)d_in[4];
    float*       out    = (float*)d_out;

    cudaFuncSetAttribute(gemm_kernel, cudaFuncAttributeMaxDynamicSharedMemorySize, SMEM_BYTES);

    prep_x_kernel<<<M_DIM, 256>>>(x);
    prep_w_kernel<<<(NF_DIM * (NX_DIM / 2) / 4) / 256, 256>>>(packed, zeros);
    gemm_kernel<<<64 * 64, 256, SMEM_BYTES>>>(out, scales, bias);
}

// round 7
// speedup vs baseline: 6.5382x; 6.5382x over previous
#include <cuda_runtime.h>
#include <cuda_fp16.h>
#include <cstdint>

// ---------------- problem constants ----------------
#define NF_DIM 8192
#define NX_DIM 2048
#define M_DIM  8192
#define BK     64
#define NITER  (NX_DIM / BK)      // 32
#define STAGE_BYTES 32768         // A 16K | B 16K
#define SMEM_BYTES (2 * STAGE_BYTES + 1024)

// ---------------- scratch (device globals; no cudaMalloc allowed) ----------------
static __device__ __align__(256) __half g_A[(size_t)M_DIM * NX_DIM];   // x as fp16
static __device__ __align__(256) __half g_B[(size_t)NF_DIM * NX_DIM];  // s*(q-z) as fp16

// ---------------- helpers ----------------
static __device__ __forceinline__ uint32_t smem_u32(const void* p) {
    uint32_t a;
    asm("{ .reg .u64 t; cvta.to.shared.u64 t, %1; cvt.u32.u64 %0, t; }" : "=r"(a) : "l"(p));
    return a;
}
#define SWZ(o) ((o) ^ ((((uint32_t)(o)) >> 3) & 0x70u))

static __device__ __forceinline__ void cpasync16(uint32_t s, const void* g) {
    asm volatile("cp.async.cg.shared.global [%0], [%1], 16;" :: "r"(s), "l"(g));
}
static __device__ __forceinline__ void cp_commit() {
    asm volatile("cp.async.commit_group;" ::: "memory");
}
static __device__ __forceinline__ void cp_wait1() {
    asm volatile("cp.async.wait_group 1;" ::: "memory");
}
static __device__ __forceinline__ void cp_wait0() {
    asm volatile("cp.async.wait_group 0;" ::: "memory");
}
static __device__ __forceinline__ void ldm4(uint32_t* r, uint32_t addr) {
    asm volatile("ldmatrix.sync.aligned.m8n8.x4.shared.b16 {%0,%1,%2,%3}, [%4];"
                 : "=r"(r[0]), "=r"(r[1]), "=r"(r[2]), "=r"(r[3]) : "r"(addr));
}
static __device__ __forceinline__ void mma16816(float* c, const uint32_t* a, uint32_t b0, uint32_t b1) {
    asm volatile(
        "mma.sync.aligned.m16n8k16.row.col.f32.f16.f16.f32 "
        "{%0,%1,%2,%3}, {%4,%5,%6,%7}, {%8,%9}, {%0,%1,%2,%3};"
        : "+f"(c[0]), "+f"(c[1]), "+f"(c[2]), "+f"(c[3])
        : "r"(a[0]), "r"(a[1]), "r"(a[2]), "r"(a[3]), "r"(b0), "r"(b1));
}

// ---------------- prep 1: x -> fp16 ----------------
__global__ __launch_bounds__(256) void prep_x_kernel(const float* __restrict__ x) {
    size_t i = ((size_t)blockIdx.x * blockDim.x + threadIdx.x) * 8;
    float4 u0 = *(const float4*)(x + i);
    float4 u1 = *(const float4*)(x + i + 4);
    __half2 h0 = __float22half2_rn(make_float2(u0.x, u0.y));
    __half2 h1 = __float22half2_rn(make_float2(u0.z, u0.w));
    __half2 h2 = __float22half2_rn(make_float2(u1.x, u1.y));
    __half2 h3 = __float22half2_rn(make_float2(u1.z, u1.w));
    uint4 o;
    o.x = *(uint32_t*)&h0; o.y = *(uint32_t*)&h1;
    o.z = *(uint32_t*)&h2; o.w = *(uint32_t*)&h3;
    *(uint4*)(g_A + i) = o;
}

// ---------------- prep 2: W = s*(q-z) -> fp16 ----------------
// packed[n][j]: one byte per int32, low nibble = weight 2j, high = 2j+1.
// Each thread: 4 packed ints -> 8 weights -> one 16B store. Same group (32 ints/group).
__global__ __launch_bounds__(256) void prep_w_kernel(const int* __restrict__ packed,
                                                     const float* __restrict__ scales,
                                                     const int* __restrict__ zeros) {
    size_t i = (size_t)blockIdx.x * blockDim.x + threadIdx.x;  // over NF*1024/4
    int4 p = ((const int4*)packed)[i];
    int n  = (int)((i * 4) >> 10);
    int j0 = (int)((i * 4) & 1023);
    int g  = j0 >> 5;
    float s  = scales[n * 32 + g];
    float zs = (float)zeros[n * 32 + g] * s;

    int pp[4] = {p.x, p.y, p.z, p.w};
    uint32_t w[4];
    #pragma unroll
    for (int q = 0; q < 4; q++) {
        float f0 = (float)(pp[q] & 15) * s - zs;
        float f1 = (float)((pp[q] >> 4) & 15) * s - zs;
        __half2 hh = __float22half2_rn(make_float2(f0, f1));
        w[q] = *(uint32_t*)&hh;
    }
    uint4 o; o.x = w[0]; o.y = w[1]; o.z = w[2]; o.w = w[3];
    *(uint4*)(g_B + (size_t)n * NX_DIM + (size_t)j0 * 2) = o;
}

// ---------------- GEMM: D = A @ B^T + bias, single-pass fp16 HMMA ----------------
// 256 threads = 8 warps, warp grid 2(M) x 4(N), warp tile 64x32. 2 CTAs/SM.
__global__ __launch_bounds__(256, 2)
void gemm_kernel(float* __restrict__ out, const float* __restrict__ bias) {
    extern __shared__ char smem[];
    const uint32_t sb = smem_u32(smem);
    const uint32_t TILE0 = (sb + 1023) & ~1023u;

    const int tid = threadIdx.x;
    const int wid = tid >> 5, lid = tid & 31;
    const int warp_m = wid & 1;
    const int warp_n = wid >> 1;

    const int t  = blockIdx.x;
    const int bm = ((t >> 9) << 3) | (t & 7);   // 8-wide M supertiles: B panel L2-resident
    const int bn = (t >> 3) & 63;

    const char* gA = (const char*)(g_A + (size_t)bm * 128 * NX_DIM);
    const char* gB = (const char*)(g_B + (size_t)bn * 128 * NX_DIM);

    // stage loader: A tile (128 rows x 64 halves = 16KB) + B tile
    auto load_stage = [&](int j, int slot) {
        const uint32_t s0 = TILE0 + slot * STAGE_BYTES;
        #pragma unroll
        for (int i = 0; i < 4; i++) {
            const int c   = tid + i * 256;       // 0..1023: 16B chunk id
            const int row = c >> 3;
            const int seg = c & 7;
            const uint32_t so = SWZ((uint32_t)(row * 128 + seg * 16));
            const size_t go = (size_t)row * (NX_DIM * 2) + (size_t)j * (BK * 2) + seg * 16;
            cpasync16(s0 +         so, gA + go);
            cpasync16(s0 + 16384 + so, gB + go);
        }
        cp_commit();
    };

    float acc[4][4][4];
    #pragma unroll
    for (int a = 0; a < 4; a++)
        #pragma unroll
        for (int b = 0; b < 4; b++)
            #pragma unroll
            for (int c = 0; c < 4; c++) acc[a][b][c] = 0.f;

    // ldmatrix lane addressing (elements)
    const int laneA_row = (lid & 7) + ((lid >> 3) & 1) * 8;
    const int laneA_k8  = ((lid >> 4) & 1) * 8;
    const int laneB_row = (lid & 7) + ((lid >> 4) & 1) * 8;
    const int laneB_k8  = ((lid >> 3) & 1) * 8;

    load_stage(0, 0);

    #pragma unroll 1
    for (int j = 0; j < NITER; j++) {
        if (j + 1 < NITER) { load_stage(j + 1, (j + 1) & 1); cp_wait1(); }
        else               { cp_wait0(); }
        __syncthreads();

        const uint32_t s0 = TILE0 + (j & 1) * STAGE_BYTES;
        const uint32_t Ab = s0, Bb = s0 + 16384;

        #pragma unroll
        for (int ks = 0; ks < 4; ks++) {
            uint32_t af[4][4], bf[2][4];
            #pragma unroll
            for (int mt = 0; mt < 4; mt++) {
                const uint32_t off = SWZ((uint32_t)((warp_m * 64 + mt * 16 + laneA_row) * 128
                                                    + (ks * 16 + laneA_k8) * 2));
                ldm4(af[mt], Ab + off);
            }
            #pragma unroll
            for (int h = 0; h < 2; h++) {
                const uint32_t off = SWZ((uint32_t)((warp_n * 32 + h * 16 + laneB_row) * 128
                                                    + (ks * 16 + laneB_k8) * 2));
                ldm4(bf[h], Bb + off);
            }
            #pragma unroll
            for (int mt = 0; mt < 4; mt++)
                #pragma unroll
                for (int nt = 0; nt < 4; nt++) {
                    const uint32_t b0 = bf[nt >> 1][(nt & 1) * 2];
                    const uint32_t b1 = bf[nt >> 1][(nt & 1) * 2 + 1];
                    mma16816(acc[mt][nt], af[mt], b0, b1);
                }
        }
        __syncthreads();
    }

    // ---- epilogue: add bias, store fp32 ----
    const int gm0 = bm * 128 + warp_m * 64 + (lid >> 2);
    const int gn0 = bn * 128 + warp_n * 32 + (lid & 3) * 2;
    #pragma unroll
    for (int nt = 0; nt < 4; nt++) {
        const int gn = gn0 + nt * 8;
        const float2 bv = *(const float2*)(bias + gn);
        #pragma unroll
        for (int mt = 0; mt < 4; mt++) {
            const int gm = gm0 + mt * 16;
            float2 v0, v1;
            v0.x = acc[mt][nt][0] + bv.x;  v0.y = acc[mt][nt][1] + bv.y;
            v1.x = acc[mt][nt][2] + bv.x;  v1.y = acc[mt][nt][3] + bv.y;
            *(float2*)(out + (size_t)gm * NF_DIM + gn)       = v0;
            *(float2*)(out + (size_t)(gm + 8) * NF_DIM + gn) = v1;
        }
    }
}

// ---------------- launch ----------------
extern "C" void kernel_launch(void* const* d_in, const int* in_sizes, int n_in,
                              void* d_out, int out_size) {
    const float* x      = (const float*)d_in[0];
    const int*   packed = (const int*)d_in[1];
    const float* scales = (const float*)d_in[2];
    const int*   zeros  = (const int*)d_in[3];
    const float* bias   = (const float*)d_in[4];
    float*       out    = (float*)d_out;

    cudaFuncSetAttribute(gemm_kernel, cudaFuncAttributeMaxDynamicSharedMemorySize, SMEM_BYTES);

    prep_x_kernel<<<(M_DIM * NX_DIM / 8) / 256, 256>>>(x);
    prep_w_kernel<<<(NF_DIM * 1024 / 4) / 256, 256>>>(packed, scales, zeros);
    gemm_kernel<<<64 * 64, 256, SMEM_BYTES>>>(out, bias);
}